// round 1
// baseline (speedup 1.0000x reference)
#include <cuda_runtime.h>
#include <math.h>

// Problem dims (fixed by the dataset)
constexpr int CB = 8;     // batch
constexpr int CS = 1024;  // seq len
constexpr int CE = 512;   // embed
constexpr int CH = 16;    // heads
constexpr int CD = 32;    // head dim
constexpr int CL = CS;    // block_len == seq_len
constexpr int CBH = CB * CH;

// Scratch for projected q/k/v in [b,h,l,d] layout (16 MB each; static device
// globals — no allocation inside kernel_launch).
__device__ float g_q[CB * CH * CL * CD];
__device__ float g_k[CB * CH * CL * CD];
__device__ float g_v[CB * CH * CL * CD];

// ---------------------------------------------------------------------------
// Projection GEMM: y = x @ W^T   (x: [8192,512], W: [512(out),512(in)])
// Result scattered directly into [b, h, s, d] layout of g_q/g_k/g_v.
// 64x64 tile, BK=16, 256 threads, 4x4 register tile per thread.
// ---------------------------------------------------------------------------
constexpr int PBM = 64;
constexpr int PBN = 64;
constexpr int PBK = 16;

__global__ __launch_bounds__(256) void proj_kernel(const float* __restrict__ x,
                                                   const float* __restrict__ W,
                                                   int which) {
    float* outp = (which == 0) ? g_q : (which == 1) ? g_k : g_v;

    __shared__ float As[PBK][PBM];
    __shared__ float Bs[PBK][PBN];

    const int bm = blockIdx.x * PBM;   // row (b*S+s) tile base
    const int bn = blockIdx.y * PBN;   // output-feature tile base
    const int tid = threadIdx.x;
    const int tx = tid & 15;
    const int ty = tid >> 4;

    float acc[4][4] = {};

    const int lrow = tid >> 2;          // 0..63
    const int lk   = (tid & 3) * 4;     // 0,4,8,12

    for (int k0 = 0; k0 < CE; k0 += PBK) {
        // Load x tile (64 rows x 16 k), transposed into As[k][m]
        float4 a = *(const float4*)&x[(size_t)(bm + lrow) * CE + k0 + lk];
        As[lk + 0][lrow] = a.x;
        As[lk + 1][lrow] = a.y;
        As[lk + 2][lrow] = a.z;
        As[lk + 3][lrow] = a.w;
        // Load W tile (64 out-rows x 16 k), transposed into Bs[k][n]
        float4 b = *(const float4*)&W[(size_t)(bn + lrow) * CE + k0 + lk];
        Bs[lk + 0][lrow] = b.x;
        Bs[lk + 1][lrow] = b.y;
        Bs[lk + 2][lrow] = b.z;
        Bs[lk + 3][lrow] = b.w;
        __syncthreads();

#pragma unroll
        for (int k = 0; k < PBK; k++) {
            float4 av = *(const float4*)&As[k][ty * 4];
            float4 bv = *(const float4*)&Bs[k][tx * 4];
            float ar[4] = {av.x, av.y, av.z, av.w};
            float br[4] = {bv.x, bv.y, bv.z, bv.w};
#pragma unroll
            for (int i = 0; i < 4; i++)
#pragma unroll
                for (int j = 0; j < 4; j++) acc[i][j] += ar[i] * br[j];
        }
        __syncthreads();
    }

    // Scatter into [b, h, s, d]; 4 consecutive d per thread-row -> float4 store
#pragma unroll
    for (int i = 0; i < 4; i++) {
        const int n = bm + ty * 4 + i;       // b*S + s
        const int bb = n >> 10;              // / 1024
        const int ss = n & 1023;
        const int obase = bn + tx * 4;       // 4 consecutive outputs, same head
        const int hh = obase >> 5;
        const int dd = obase & 31;
        float4 v = make_float4(acc[i][0], acc[i][1], acc[i][2], acc[i][3]);
        *(float4*)&outp[(((size_t)bb * CH + hh) * CL + ss) * CD + dd] = v;
    }
}

// ---------------------------------------------------------------------------
// Flash attention with relative position bias.
// Block: 64 query rows (8 warps x 8 rows), K tiles of 32 (lane = key col).
// Srel[i,j] = q_i . Er[j - i + L - 1]; per (q-tile, k-tile) the needed Er rows
// are one contiguous slab of 95 rows starting at j0 - i0 + 960 (always valid).
// ---------------------------------------------------------------------------
constexpr int AM = 64;   // query rows per block
constexpr int AN = 32;   // key cols per tile
constexpr int ERW = AM + AN - 1;  // 95 Er rows per slab

__global__ __launch_bounds__(256) void attn_kernel(const float* __restrict__ Er,
                                                   float* __restrict__ out) {
    __shared__ float Qs[AM][CD];          // [i][d]  (broadcast reads)
    __shared__ float Kt[CD][AN + 1];      // [d][j]  (+1 pad: conflict-free fill)
    __shared__ float Vs[AN][CD];          // [j][d]
    __shared__ float Ers[CD][ERW];        // [d][t]

    const int bh = blockIdx.y;            // b*H + h
    const int i0 = blockIdx.x * AM;
    const int tid = threadIdx.x;
    const int w = tid >> 5;
    const int lane = tid & 31;

    const float* qptr = g_q + (size_t)bh * CL * CD;
    const float* kptr = g_k + (size_t)bh * CL * CD;
    const float* vptr = g_v + (size_t)bh * CL * CD;

    // Load Q tile (64 x 32)
    {
        const int r = tid >> 2;
        const int d0 = (tid & 3) * 8;
        *(float4*)&Qs[r][d0]     = *(const float4*)&qptr[(size_t)(i0 + r) * CD + d0];
        *(float4*)&Qs[r][d0 + 4] = *(const float4*)&qptr[(size_t)(i0 + r) * CD + d0 + 4];
    }

    float mrow[8], lrow[8], orow[8];
#pragma unroll
    for (int r = 0; r < 8; r++) { mrow[r] = -INFINITY; lrow[r] = 0.f; orow[r] = 0.f; }

    const float scale = 0.17677669529663688f;  // 1/sqrt(32)

    for (int jt = 0; jt < CL / AN; jt++) {
        const int j0 = jt * AN;
        __syncthreads();  // protects Qs on iter 0, Kt/Vs/Ers reuse afterwards

        // Load K tile transposed + V tile
        {
            const int row = tid >> 3;           // 0..31 (key index)
            const int c4 = (tid & 7) * 4;       // d base
            float4 kv = *(const float4*)&kptr[(size_t)(j0 + row) * CD + c4];
            Kt[c4 + 0][row] = kv.x;
            Kt[c4 + 1][row] = kv.y;
            Kt[c4 + 2][row] = kv.z;
            Kt[c4 + 3][row] = kv.w;
            *(float4*)&Vs[row][c4] = *(const float4*)&vptr[(size_t)(j0 + row) * CD + c4];
        }
        // Load Er slab: rows base..base+94, stored transposed [d][t]
        const int base = j0 - i0 + (CL - AM);   // in [0, 1952]
        for (int idx = tid; idx < ERW * (CD / 4); idx += 256) {
            const int t = idx >> 3;
            const int c4 = (idx & 7) * 4;
            float4 ev = *(const float4*)&Er[(size_t)(base + t) * CD + c4];
            Ers[c4 + 0][t] = ev.x;
            Ers[c4 + 1][t] = ev.y;
            Ers[c4 + 2][t] = ev.z;
            Ers[c4 + 3][t] = ev.w;
        }
        __syncthreads();

#pragma unroll
        for (int r = 0; r < 8; r++) {
            const int iloc = w * 8 + r;
            const int t = lane + (AM - 1) - iloc;   // 0..94
            float s = 0.f;
#pragma unroll
            for (int d = 0; d < CD; d++) {
                const float qv = Qs[iloc][d];       // broadcast
                s += qv * Kt[d][lane];              // conflict-free
                s += qv * Ers[d][t];                // conflict-free
            }
            s *= scale;

            // online softmax across the 32 keys of this tile
            float mt = s;
#pragma unroll
            for (int off = 16; off; off >>= 1)
                mt = fmaxf(mt, __shfl_xor_sync(0xffffffffu, mt, off));
            const float mnew = fmaxf(mrow[r], mt);
            const float p = __expf(s - mnew);
            float ps = p;
#pragma unroll
            for (int off = 16; off; off >>= 1)
                ps += __shfl_xor_sync(0xffffffffu, ps, off);
            const float alpha = __expf(mrow[r] - mnew);  // 0 when mrow == -inf
            lrow[r] = lrow[r] * alpha + ps;
            mrow[r] = mnew;

            float acc = orow[r] * alpha;
#pragma unroll
            for (int j = 0; j < AN; j++)
                acc += __shfl_sync(0xffffffffu, p, j) * Vs[j][lane];
            orow[r] = acc;
        }
    }

    // Write out: out[b][s][h*32 + d], d = lane (coalesced)
    const int bb = bh >> 4;
    const int hh = bh & 15;
#pragma unroll
    for (int r = 0; r < 8; r++) {
        const int i = i0 + w * 8 + r;
        out[((size_t)bb * CS + i) * CE + hh * CD + lane] = orow[r] / lrow[r];
    }
}

// ---------------------------------------------------------------------------
extern "C" void kernel_launch(void* const* d_in, const int* in_sizes, int n_in,
                              void* d_out, int out_size) {
    const float* x  = (const float*)d_in[0];
    const float* Wq = (const float*)d_in[1];
    const float* Wk = (const float*)d_in[2];
    const float* Wv = (const float*)d_in[3];
    const float* Er = (const float*)d_in[4];
    float* out = (float*)d_out;

    dim3 pgrid(CB * CS / PBM, CE / PBN);   // (128, 8)
    proj_kernel<<<pgrid, 256>>>(x, Wq, 0);
    proj_kernel<<<pgrid, 256>>>(x, Wk, 1);
    proj_kernel<<<pgrid, 256>>>(x, Wv, 2);

    dim3 agrid(CL / AM, CBH);              // (16, 128)
    attn_kernel<<<agrid, 256>>>(Er, out);
}

// round 2
// speedup vs baseline: 2.0521x; 2.0521x over previous
#include <cuda_runtime.h>
#include <math.h>

// Problem dims (fixed by the dataset)
constexpr int CB = 8;     // batch
constexpr int CS = 1024;  // seq len
constexpr int CE = 512;   // embed
constexpr int CH = 16;    // heads
constexpr int CD = 32;    // head dim
constexpr int CL = CS;    // block_len == seq_len
constexpr int CBH = CB * CH;

// Scratch for projected q/k/v in [b,h,l,d] layout
__device__ float g_q[CB * CH * CL * CD];
__device__ float g_k[CB * CH * CL * CD];
__device__ float g_v[CB * CH * CL * CD];

// ---------------------------------------------------------------------------
// Projection GEMM: y = x @ W^T  (unchanged from R1 — fp32, ~360us; attn first)
// ---------------------------------------------------------------------------
constexpr int PBM = 64;
constexpr int PBN = 64;
constexpr int PBK = 16;

__global__ __launch_bounds__(256) void proj_kernel(const float* __restrict__ x,
                                                   const float* __restrict__ W,
                                                   int which) {
    float* outp = (which == 0) ? g_q : (which == 1) ? g_k : g_v;

    __shared__ float As[PBK][PBM];
    __shared__ float Bs[PBK][PBN];

    const int bm = blockIdx.x * PBM;
    const int bn = blockIdx.y * PBN;
    const int tid = threadIdx.x;
    const int tx = tid & 15;
    const int ty = tid >> 4;

    float acc[4][4] = {};

    const int lrow = tid >> 2;
    const int lk   = (tid & 3) * 4;

    for (int k0 = 0; k0 < CE; k0 += PBK) {
        float4 a = *(const float4*)&x[(size_t)(bm + lrow) * CE + k0 + lk];
        As[lk + 0][lrow] = a.x;
        As[lk + 1][lrow] = a.y;
        As[lk + 2][lrow] = a.z;
        As[lk + 3][lrow] = a.w;
        float4 b = *(const float4*)&W[(size_t)(bn + lrow) * CE + k0 + lk];
        Bs[lk + 0][lrow] = b.x;
        Bs[lk + 1][lrow] = b.y;
        Bs[lk + 2][lrow] = b.z;
        Bs[lk + 3][lrow] = b.w;
        __syncthreads();

#pragma unroll
        for (int k = 0; k < PBK; k++) {
            float4 av = *(const float4*)&As[k][ty * 4];
            float4 bv = *(const float4*)&Bs[k][tx * 4];
            float ar[4] = {av.x, av.y, av.z, av.w};
            float br[4] = {bv.x, bv.y, bv.z, bv.w};
#pragma unroll
            for (int i = 0; i < 4; i++)
#pragma unroll
                for (int j = 0; j < 4; j++) acc[i][j] += ar[i] * br[j];
        }
        __syncthreads();
    }

#pragma unroll
    for (int i = 0; i < 4; i++) {
        const int n = bm + ty * 4 + i;
        const int bb = n >> 10;
        const int ss = n & 1023;
        const int obase = bn + tx * 4;
        const int hh = obase >> 5;
        const int dd = obase & 31;
        float4 v = make_float4(acc[i][0], acc[i][1], acc[i][2], acc[i][3]);
        *(float4*)&outp[(((size_t)bb * CH + hh) * CL + ss) * CD + dd] = v;
    }
}

// ---------------------------------------------------------------------------
// tf32 mma.sync flash attention with relative position bias.
//
// Block = 128 threads (4 warps), Br=64 query rows (16/warp), Bc=64 keys/iter.
// Per iter & warp:
//   G phase: G = Q(16x32) @ ErSlab^T over an 80-wide t-window (10 n-tiles),
//            scatter the diagonal band G[i, j-i+63] into skewed smem Gs[i][j].
//   S phase: S = Q @ K^T (8 n-tiles) + Gs, online softmax (rows split across
//            lane quads, shfl_xor reduce), P staged to smem (tf32-rounded).
//   PV:      O += P(16x64) @ V(64x32), fp32 accum in fragments.
// All tf32 operands are round-to-nearest (cvt.rna) at staging to avoid the
// truncation bias of raw fp32 bit patterns.
// ---------------------------------------------------------------------------
__device__ __forceinline__ float tf32r(float f) {
    unsigned u;
    asm("cvt.rna.tf32.f32 %0, %1;" : "=r"(u) : "f"(f));
    return __uint_as_float(u);
}

__device__ __forceinline__ void mma8(float* c, const unsigned* a, unsigned b0, unsigned b1) {
    asm volatile(
        "mma.sync.aligned.m16n8k8.row.col.f32.tf32.tf32.f32 "
        "{%0,%1,%2,%3}, {%4,%5,%6,%7}, {%8,%9}, {%0,%1,%2,%3};"
        : "+f"(c[0]), "+f"(c[1]), "+f"(c[2]), "+f"(c[3])
        : "r"(a[0]), "r"(a[1]), "r"(a[2]), "r"(a[3]), "r"(b0), "r"(b1));
}

// Smem layout (floats). Pads chosen for conflict-free mma-fragment LDS:
// pattern bank = (8*(l%4) + l/4) or (8*(l/4) + l%4) -> pad % 32 == 8.
constexpr int PAD_KT = 72;    // Kt[32][72]   : K^T  [d][j]
constexpr int PAD_VS = 40;    // Vs[64][40]   : V    [j][d]
constexpr int PAD_ER = 136;   // ErT[32][136] : ErSlab^T [d][t], col 127 zeroed
constexpr int PAD_GP = 72;    // GP[64][72]   : skewed Srel, then P staging
constexpr int OFF_VS = CD * PAD_KT;            // 2304
constexpr int OFF_ER = OFF_VS + 64 * PAD_VS;   // 4864
constexpr int OFF_GP = OFF_ER + CD * PAD_ER;   // 9216
constexpr int SMEM_FLOATS = OFF_GP + 64 * PAD_GP;  // 13824 -> 55296 bytes

__global__ __launch_bounds__(128, 4) void attn_mma(const float* __restrict__ Er,
                                                   float* __restrict__ out) {
    extern __shared__ float sm[];
#define KT(d, j)  sm[(d) * PAD_KT + (j)]
#define VS(j, d)  sm[OFF_VS + (j) * PAD_VS + (d)]
#define ERT(d, t) sm[OFF_ER + (d) * PAD_ER + (t)]
#define GP(i, j)  sm[OFF_GP + (i) * PAD_GP + (j)]

    const int bh = blockIdx.y;            // b*H + h
    const int i0 = blockIdx.x * 64;
    const int tid = threadIdx.x;
    const int w = tid >> 5, lane = tid & 31;
    const int gl = lane >> 2;             // groupID (0..7)
    const int ql = lane & 3;              // thread-in-group (0..3)
    const int rw = w * 16;                // warp's row base within block
    const int tw = 48 - rw;               // warp's Er t-window base

    const float* qp = g_q + (size_t)bh * CL * CD;
    const float* kp = g_k + (size_t)bh * CL * CD;
    const float* vp = g_v + (size_t)bh * CL * CD;

    // Q A-fragments (tf32), 4 k-steps, resident for the whole block
    unsigned qa[4][4];
    {
        const int r0g = i0 + rw + gl;
#pragma unroll
        for (int ks = 0; ks < 4; ks++) {
            qa[ks][0] = __float_as_uint(tf32r(qp[(size_t)r0g * CD + ks * 8 + ql]));
            qa[ks][1] = __float_as_uint(tf32r(qp[(size_t)(r0g + 8) * CD + ks * 8 + ql]));
            qa[ks][2] = __float_as_uint(tf32r(qp[(size_t)r0g * CD + ks * 8 + ql + 4]));
            qa[ks][3] = __float_as_uint(tf32r(qp[(size_t)(r0g + 8) * CD + ks * 8 + ql + 4]));
        }
    }

    float o[4][4];
#pragma unroll
    for (int i = 0; i < 4; i++)
#pragma unroll
        for (int j = 0; j < 4; j++) o[i][j] = 0.f;
    float m0 = -INFINITY, m1 = -INFINITY, l0 = 0.f, l1 = 0.f;
    const float SCALE = 0.17677669529663688f;  // 1/sqrt(32)

    for (int jt = 0; jt < CL / 64; jt++) {
        const int j0 = jt * 64;
        const int base = j0 - i0 + (CL - 64);  // Er slab start, in [0, 1920]
        __syncthreads();

        // ---- stage K (tid<64, transposed) / V (tid>=64) ----
        if (tid < 64) {
            const float* kr = kp + (size_t)(j0 + tid) * CD;
#pragma unroll
            for (int c = 0; c < CD; c += 4) {
                float4 kv = *(const float4*)&kr[c];
                KT(c + 0, tid) = tf32r(kv.x);
                KT(c + 1, tid) = tf32r(kv.y);
                KT(c + 2, tid) = tf32r(kv.z);
                KT(c + 3, tid) = tf32r(kv.w);
            }
        } else {
            const int j = tid - 64;
            const float* vr = vp + (size_t)(j0 + j) * CD;
#pragma unroll
            for (int c = 0; c < CD; c += 4) {
                float4 vv = *(const float4*)&vr[c];
                VS(j, c + 0) = tf32r(vv.x);
                VS(j, c + 1) = tf32r(vv.y);
                VS(j, c + 2) = tf32r(vv.z);
                VS(j, c + 3) = tf32r(vv.w);
            }
        }
        // ---- stage Er slab rows [base, base+127), transposed ----
        if (tid < 127) {
            const float* er = Er + (size_t)(base + tid) * CD;
#pragma unroll
            for (int c = 0; c < CD; c += 4) {
                float4 ev = *(const float4*)&er[c];
                ERT(c + 0, tid) = tf32r(ev.x);
                ERT(c + 1, tid) = tf32r(ev.y);
                ERT(c + 2, tid) = tf32r(ev.z);
                ERT(c + 3, tid) = tf32r(ev.w);
            }
        }
        if (tid < CD) ERT(tid, 127) = 0.f;  // only w=0's last n-tile touches t=127
        __syncthreads();

        // ---- G phase: Q @ ErSlab^T over this warp's 80-wide t-window ----
        float ga[10][4];
#pragma unroll
        for (int nt = 0; nt < 10; nt++)
#pragma unroll
            for (int e = 0; e < 4; e++) ga[nt][e] = 0.f;
#pragma unroll
        for (int nt = 0; nt < 10; nt++) {
            const int tb = tw + nt * 8 + gl;
#pragma unroll
            for (int ks = 0; ks < 4; ks++) {
                unsigned b0 = __float_as_uint(ERT(ks * 8 + ql, tb));
                unsigned b1 = __float_as_uint(ERT(ks * 8 + ql + 4, tb));
                mma8(ga[nt], qa[ks], b0, b1);
            }
        }
        // scatter diagonal band into skewed Gs: Gs[i][j] = G[i][t], j = t+i-63
        {
            const int ia = rw + gl, ib = ia + 8;
#pragma unroll
            for (int nt = 0; nt < 10; nt++) {
                const int t0 = tw + nt * 8 + 2 * ql;
                const int ja = t0 + ia - 63;
                const int jb2 = t0 + ib - 63;
                if ((unsigned)ja < 64u)        GP(ia, ja)      = ga[nt][0];
                if ((unsigned)(ja + 1) < 64u)  GP(ia, ja + 1)  = ga[nt][1];
                if ((unsigned)jb2 < 64u)       GP(ib, jb2)     = ga[nt][2];
                if ((unsigned)(jb2 + 1) < 64u) GP(ib, jb2 + 1) = ga[nt][3];
            }
        }
        __syncwarp();

        // ---- S phase: Q @ K^T ----
        float sc[8][4];
#pragma unroll
        for (int nt = 0; nt < 8; nt++)
#pragma unroll
            for (int e = 0; e < 4; e++) sc[nt][e] = 0.f;
#pragma unroll
        for (int nt = 0; nt < 8; nt++) {
            const int jb = nt * 8 + gl;
#pragma unroll
            for (int ks = 0; ks < 4; ks++) {
                unsigned b0 = __float_as_uint(KT(ks * 8 + ql, jb));
                unsigned b1 = __float_as_uint(KT(ks * 8 + ql + 4, jb));
                mma8(sc[nt], qa[ks], b0, b1);
            }
        }
        // add relative bias from skewed Gs
        const int ra = rw + gl, rb = ra + 8;
#pragma unroll
        for (int nt = 0; nt < 8; nt++) {
            const int jc = nt * 8 + 2 * ql;
            float2 gA = *(float2*)&GP(ra, jc);
            float2 gB = *(float2*)&GP(rb, jc);
            sc[nt][0] += gA.x;
            sc[nt][1] += gA.y;
            sc[nt][2] += gB.x;
            sc[nt][3] += gB.y;
        }
        // ---- online softmax (rows ra / rb, reduced across lane quads) ----
        float tm0 = -INFINITY, tm1 = -INFINITY;
#pragma unroll
        for (int nt = 0; nt < 8; nt++) {
            tm0 = fmaxf(tm0, fmaxf(sc[nt][0], sc[nt][1]));
            tm1 = fmaxf(tm1, fmaxf(sc[nt][2], sc[nt][3]));
        }
        tm0 = fmaxf(tm0, __shfl_xor_sync(0xffffffffu, tm0, 1));
        tm0 = fmaxf(tm0, __shfl_xor_sync(0xffffffffu, tm0, 2));
        tm1 = fmaxf(tm1, __shfl_xor_sync(0xffffffffu, tm1, 1));
        tm1 = fmaxf(tm1, __shfl_xor_sync(0xffffffffu, tm1, 2));
        const float mn0 = fmaxf(m0, tm0), mn1 = fmaxf(m1, tm1);
        const float al0 = __expf((m0 - mn0) * SCALE);
        const float al1 = __expf((m1 - mn1) * SCALE);
        m0 = mn0; m1 = mn1;

        float s0 = 0.f, s1 = 0.f;
#pragma unroll
        for (int nt = 0; nt < 8; nt++) {
            const float p00 = tf32r(__expf((sc[nt][0] - m0) * SCALE));
            const float p01 = tf32r(__expf((sc[nt][1] - m0) * SCALE));
            const float p10 = tf32r(__expf((sc[nt][2] - m1) * SCALE));
            const float p11 = tf32r(__expf((sc[nt][3] - m1) * SCALE));
            s0 += p00 + p01;
            s1 += p10 + p11;
            const int jc = nt * 8 + 2 * ql;
            *(float2*)&GP(ra, jc) = make_float2(p00, p01);
            *(float2*)&GP(rb, jc) = make_float2(p10, p11);
        }
        s0 += __shfl_xor_sync(0xffffffffu, s0, 1);
        s0 += __shfl_xor_sync(0xffffffffu, s0, 2);
        s1 += __shfl_xor_sync(0xffffffffu, s1, 1);
        s1 += __shfl_xor_sync(0xffffffffu, s1, 2);
        l0 = l0 * al0 + s0;
        l1 = l1 * al1 + s1;
        // rescale O accumulators
#pragma unroll
        for (int nt = 0; nt < 4; nt++) {
            o[nt][0] *= al0;
            o[nt][1] *= al0;
            o[nt][2] *= al1;
            o[nt][3] *= al1;
        }
        __syncwarp();

        // ---- PV: O += P @ V ----
#pragma unroll
        for (int ks = 0; ks < 8; ks++) {
            unsigned pa[4];
            pa[0] = __float_as_uint(GP(rw + gl, ks * 8 + ql));
            pa[1] = __float_as_uint(GP(rw + gl + 8, ks * 8 + ql));
            pa[2] = __float_as_uint(GP(rw + gl, ks * 8 + ql + 4));
            pa[3] = __float_as_uint(GP(rw + gl + 8, ks * 8 + ql + 4));
#pragma unroll
            for (int nt = 0; nt < 4; nt++) {
                unsigned b0 = __float_as_uint(VS(ks * 8 + ql, nt * 8 + gl));
                unsigned b1 = __float_as_uint(VS(ks * 8 + ql + 4, nt * 8 + gl));
                mma8(o[nt], pa, b0, b1);
            }
        }
    }

    // ---- epilogue: normalize and write out[b][s][h*32+d] ----
    const float il0 = 1.f / l0, il1 = 1.f / l1;
    const int bb = bh >> 4, hh = bh & 15;
    const int ro0 = i0 + rw + gl, ro1 = ro0 + 8;
    float* op0 = out + ((size_t)bb * CS + ro0) * CE + hh * CD;
    float* op1 = out + ((size_t)bb * CS + ro1) * CE + hh * CD;
#pragma unroll
    for (int nt = 0; nt < 4; nt++) {
        const int dcol = nt * 8 + 2 * ql;
        *(float2*)&op0[dcol] = make_float2(o[nt][0] * il0, o[nt][1] * il0);
        *(float2*)&op1[dcol] = make_float2(o[nt][2] * il1, o[nt][3] * il1);
    }
#undef KT
#undef VS
#undef ERT
#undef GP
}

// ---------------------------------------------------------------------------
extern "C" void kernel_launch(void* const* d_in, const int* in_sizes, int n_in,
                              void* d_out, int out_size) {
    const float* x  = (const float*)d_in[0];
    const float* Wq = (const float*)d_in[1];
    const float* Wk = (const float*)d_in[2];
    const float* Wv = (const float*)d_in[3];
    const float* Er = (const float*)d_in[4];
    float* out = (float*)d_out;

    dim3 pgrid(CB * CS / PBM, CE / PBN);   // (128, 8)
    proj_kernel<<<pgrid, 256>>>(x, Wq, 0);
    proj_kernel<<<pgrid, 256>>>(x, Wk, 1);
    proj_kernel<<<pgrid, 256>>>(x, Wv, 2);

    constexpr int smem_bytes = SMEM_FLOATS * sizeof(float);  // 55296
    cudaFuncSetAttribute(attn_mma, cudaFuncAttributeMaxDynamicSharedMemorySize,
                         smem_bytes);
    dim3 agrid(CL / 64, CBH);              // (16, 128)
    attn_mma<<<agrid, 128, smem_bytes>>>(Er, out);
}